// round 6
// baseline (speedup 1.0000x reference)
#include <cuda_runtime.h>

#define N_NODES 48
#define N_EDGES 192
#define DIM     1024
#define NN      (N_NODES * N_NODES)   // 2304
#define EE      (N_EDGES * N_EDGES)   // 36864
#define OUT_DIM NN                    // 2304
#define SPLITK  16
#define KC      (DIM / SPLITK)        // 64
#define N4      ((OUT_DIM * OUT_DIM) / 4)   // 1,327,104 float4
#define NBLK    240
#define NTHR    256
#define GEMM_BLOCKS 144               // 3 x 3 x 16
#define NROWS   (2 * DIM)             // 2048 coeff rows

// Scratch (no cudaMalloc allowed)
__device__ float g_cn[DIM];
__device__ float g_ce[DIM];
__device__ float g_Mp[NN];
__device__ float g_MePart[SPLITK][EE];
// Cumulative barrier counters: ticket scheme, never reset -> safe across
// graph replays (each replay adds exactly NBLK arrivals per barrier).
__device__ unsigned g_bar1;
__device__ unsigned g_bar2;

__device__ __forceinline__ float softplus_act(float x) {
    // relu(softplus(x) - 0.5)
    float sp = (x > 20.f) ? x : log1pf(expf(x));
    float v = sp - 0.5f;
    return v > 0.f ? v : 0.f;
}

// Grid-wide barrier. Requires all NBLK blocks co-resident (guaranteed:
// launch_bounds(256,2) => regs<=128, smem ~9KB => >=2 blocks/SM => capacity
// >= 296 >= 240, so the whole grid is in wave 1).
__device__ __forceinline__ void grid_barrier(unsigned* ctr) {
    __syncthreads();
    if (threadIdx.x == 0) {
        __threadfence();                                   // release prior writes
        unsigned tkt = atomicAdd(ctr, 1u) + 1u;
        unsigned target = ((tkt + NBLK - 1u) / NBLK) * NBLK;
        volatile unsigned* vc = (volatile unsigned*)ctr;
        while ((int)(*vc - target) < 0) { }                // wraparound-safe
        __threadfence();                                   // acquire
    }
    __syncthreads();
}

// ---------------------------------------------------------------------------
// Single persistent kernel: coeff + zero-fill | barrier | GEMM + Mp | barrier
// | scatter.
// ---------------------------------------------------------------------------
__global__ void __launch_bounds__(NTHR, 2)
k_all(const float* __restrict__ x1, const float* __restrict__ x2,
      const float* __restrict__ ef1, const float* __restrict__ ef2,
      const float* __restrict__ gw,
      const float* __restrict__ Wn, const float* __restrict__ bn,
      const float* __restrict__ We, const float* __restrict__ be,
      const int* __restrict__ ei1, const int* __restrict__ ei2,
      float* __restrict__ M) {
    __shared__ float4 As[16][17];
    __shared__ float4 Bs[16][17];
    float* sred = (float*)Bs;        // phase-A scratch (re-used by GEMM later)

    int t = threadIdx.x;
    int b = blockIdx.x;
    int lane = t & 31, warp = t >> 5;

    // ================= Phase A: coeff rows + zero-fill =====================
    // Block b handles rows {b, b+240, ...}: 9 rows for b<128, else 8.
    // Each thread loads one float4 per row (256 float4 = 1024 floats/row).
    {
        float4 g4 = ((const float4*)gw)[t];
        int nr = (b < 128) ? 9 : 8;
        float4 wv[9];
#pragma unroll
        for (int i = 0; i < 9; i++) {
            if (i < nr) {
                int r = b + NBLK * i;
                const float* W = (r < DIM) ? Wn : We;
                int rr = (r < DIM) ? r : r - DIM;
                wv[i] = ((const float4*)(W + rr * DIM))[t];
            }
        }
        // zero-fill output; stores overlap the in-flight weight loads
        {
            float4 z = make_float4(0.f, 0.f, 0.f, 0.f);
            float4* out4 = (float4*)M;
            for (int i = b * NTHR + t; i < N4; i += NBLK * NTHR) out4[i] = z;
        }
#pragma unroll
        for (int i = 0; i < 9; i++) {
            if (i < nr) {
                float4 a = wv[i];
                float acc = a.x * g4.x + a.y * g4.y + a.z * g4.z + a.w * g4.w;
#pragma unroll
                for (int o = 16; o; o >>= 1) acc += __shfl_xor_sync(0xffffffffu, acc, o);
                if (lane == 0) sred[i * 8 + warp] = acc;
            }
        }
        __syncthreads();
        if (t < nr) {
            float s = 0.f;
#pragma unroll
            for (int j = 0; j < 8; j++) s += sred[t * 8 + j];
            int r = b + NBLK * t;
            if (r < DIM) g_cn[r]       = tanhf(s + bn[r]);
            else         g_ce[r - DIM] = tanhf(s + be[r - DIM]);
        }
    }

    grid_barrier(&g_bar1);

    // ================= Phase B: Me split-K GEMM / Mp =======================
    if (b < GEMM_BLOCKS) {
        // C[m,n] = sum_k ef1[m,k]*ce[k]*ef2[n,k]; 64x64 tile, k-major smem,
        // contiguous 4x4 C tile per thread (2x LDS.128 + 16 FFMA per kk).
        float* Asf = (float*)As;        // row stride 68 floats
        float* Bsf = (float*)Bs;

        int tx = t & 15, ty = t >> 4;
        int bx = b % 3;
        int by = (b / 3) % 3;
        int kz = b / 9;                 // 0..15
        int lr = t >> 2;                // 0..63 (tile row this thread loads)
        int lc = (t & 3) * 4;           // 0,4,8,12 (k-chunk base)
        float acc[4][4] = {};
        int k0 = kz * KC;
        const float* Arow = ef1 + (by * 64 + lr) * DIM;
        const float* Brow = ef2 + (bx * 64 + lr) * DIM;

        for (int kb = k0; kb < k0 + KC; kb += 16) {
            float4 c4 = *(const float4*)(g_ce + kb + lc);
            float4 a4 = *(const float4*)(Arow + kb + lc);
            float4 b4 = *(const float4*)(Brow + kb + lc);
            a4.x *= c4.x; a4.y *= c4.y; a4.z *= c4.z; a4.w *= c4.w;
            Asf[(lc + 0) * 68 + lr] = a4.x;
            Asf[(lc + 1) * 68 + lr] = a4.y;
            Asf[(lc + 2) * 68 + lr] = a4.z;
            Asf[(lc + 3) * 68 + lr] = a4.w;
            Bsf[(lc + 0) * 68 + lr] = b4.x;
            Bsf[(lc + 1) * 68 + lr] = b4.y;
            Bsf[(lc + 2) * 68 + lr] = b4.z;
            Bsf[(lc + 3) * 68 + lr] = b4.w;
            __syncthreads();
#pragma unroll
            for (int kk = 0; kk < 16; kk++) {
                float4 av = As[kk][ty];
                float4 bv = Bs[kk][tx];
                float a[4] = {av.x, av.y, av.z, av.w};
                float bb[4] = {bv.x, bv.y, bv.z, bv.w};
#pragma unroll
                for (int j = 0; j < 4; j++)
#pragma unroll
                    for (int i = 0; i < 4; i++)
                        acc[j][i] += a[j] * bb[i];
            }
            __syncthreads();
        }

        float* outp = g_MePart[kz];
#pragma unroll
        for (int j = 0; j < 4; j++) {
            int m = by * 64 + 4 * ty + j;
            int n = bx * 64 + 4 * tx;
            *(float4*)(outp + m * N_EDGES + n) =
                make_float4(acc[j][0], acc[j][1], acc[j][2], acc[j][3]);
        }
    } else {
        // Mp: 768 warps, 3 outputs per warp (same m, A row reused)
        int w = (b - GEMM_BLOCKS) * 8 + warp;   // 0..767
        int idx0 = w * 3;
        int m = idx0 / N_NODES, n0 = idx0 % N_NODES;  // 48 % 3 == 0 -> same m
        const float4* A  = (const float4*)(x1 + m * DIM);
        const float4* B0 = (const float4*)(x2 + n0 * DIM);
        const float4* C  = (const float4*)g_cn;
        float s0 = 0.f, s1 = 0.f, s2 = 0.f;
#pragma unroll
        for (int i = 0; i < 8; i++) {
            int k = i * 32 + lane;
            float4 a = A[k], c = C[k];
            a.x *= c.x; a.y *= c.y; a.z *= c.z; a.w *= c.w;
            float4 b0 = B0[k], b1 = B0[256 + k], b2 = B0[512 + k];
            s0 += a.x * b0.x + a.y * b0.y + a.z * b0.z + a.w * b0.w;
            s1 += a.x * b1.x + a.y * b1.y + a.z * b1.z + a.w * b1.w;
            s2 += a.x * b2.x + a.y * b2.y + a.z * b2.z + a.w * b2.w;
        }
#pragma unroll
        for (int o = 16; o; o >>= 1) {
            s0 += __shfl_xor_sync(0xffffffffu, s0, o);
            s1 += __shfl_xor_sync(0xffffffffu, s1, o);
            s2 += __shfl_xor_sync(0xffffffffu, s2, o);
        }
        if (lane == 0) {
            g_Mp[idx0 + 0] = softplus_act(s0);
            g_Mp[idx0 + 1] = softplus_act(s1);
            g_Mp[idx0 + 2] = softplus_act(s2);
        }
    }

    grid_barrier(&g_bar2);

    // ================= Phase C: scatter ====================================
    // value for pair (j1,j2) is Me.flat[j2*192+j1]:
    //   M[head2[j2]*48+head1[j1], tail2[j2]*48+tail1[j1]] += act(.)
    for (int idx = b * NTHR + t; idx < EE + NN; idx += NBLK * NTHR) {
        if (idx < EE) {
            float s = 0.f;
#pragma unroll
            for (int z = 0; z < SPLITK; z++) s += g_MePart[z][idx];
            float v = softplus_act(s);
            if (v > 0.f) {
                int j2 = idx / N_EDGES;   // row of Me flat view
                int j1 = idx % N_EDGES;   // col of Me flat view
                int r = ei2[j2] * N_NODES + ei1[j1];                      // heads
                int c = ei2[N_EDGES + j2] * N_NODES + ei1[N_EDGES + j1];  // tails
                atomicAdd(M + r * OUT_DIM + c, v);
            }
        } else {
            int a = idx - EE;
            atomicAdd(M + a * (OUT_DIM + 1), g_Mp[a]);
        }
    }
}

extern "C" void kernel_launch(void* const* d_in, const int* in_sizes, int n_in,
                              void* d_out, int out_size) {
    const float* x1  = (const float*)d_in[0];
    const float* x2  = (const float*)d_in[1];
    const float* ef1 = (const float*)d_in[2];
    const float* ef2 = (const float*)d_in[3];
    const float* gw  = (const float*)d_in[4];
    const float* Wn  = (const float*)d_in[5];
    const float* bn  = (const float*)d_in[6];
    const float* We  = (const float*)d_in[7];
    const float* be  = (const float*)d_in[8];
    const int*   ei1 = (const int*)d_in[9];
    const int*   ei2 = (const int*)d_in[10];
    float* M = (float*)d_out;

    k_all<<<NBLK, NTHR>>>(x1, x2, ef1, ef2, gw, Wn, bn, We, be, ei1, ei2, M);
}

// round 7
// speedup vs baseline: 1.0480x; 1.0480x over previous
#include <cuda_runtime.h>

#define N_NODES 48
#define N_EDGES 192
#define DIM     1024
#define NN      (N_NODES * N_NODES)   // 2304
#define EE      (N_EDGES * N_EDGES)   // 36864
#define OUT_DIM NN                    // 2304
#define SPLITK  16
#define KC      (DIM / SPLITK)        // 64
#define N4      ((OUT_DIM * OUT_DIM) / 4)   // 1,327,104 float4
#define NBLK    240
#define NTHR    256
#define GEMM_BLOCKS 144               // 3 x 3 x 16
#define NROWS   (2 * DIM)             // 2048 coeff rows

// Scratch (no cudaMalloc allowed)
__device__ float g_cn[DIM];
__device__ float g_ce[DIM];
__device__ float g_Mp[NN];
__device__ float g_MePart[SPLITK][EE];
// Cumulative barrier counters: ticket scheme, never reset -> safe across
// graph replays (each replay adds exactly NBLK arrivals per barrier).
__device__ unsigned g_bar1;
__device__ unsigned g_bar2;

__device__ __forceinline__ float softplus_act(float x) {
    // relu(softplus(x) - 0.5)
    float sp = (x > 20.f) ? x : log1pf(expf(x));
    float v = sp - 0.5f;
    return v > 0.f ? v : 0.f;
}

// Grid-wide barrier. Requires all NBLK blocks co-resident (guaranteed:
// launch_bounds(256,2) => regs<=128, smem ~9KB => >=2 blocks/SM => capacity
// >= 296 >= 240, so the whole grid is in wave 1).
__device__ __forceinline__ void grid_barrier(unsigned* ctr) {
    __syncthreads();
    if (threadIdx.x == 0) {
        __threadfence();                                   // release prior writes
        unsigned tkt = atomicAdd(ctr, 1u) + 1u;
        unsigned target = ((tkt + NBLK - 1u) / NBLK) * NBLK;
        volatile unsigned* vc = (volatile unsigned*)ctr;
        while ((int)(*vc - target) < 0) { }                // wraparound-safe
        __threadfence();                                   // acquire
    }
    __syncthreads();
}

// ---------------------------------------------------------------------------
// Single persistent kernel: coeff + zero-fill | barrier | GEMM + Mp | barrier
// | scatter.
// ---------------------------------------------------------------------------
__global__ void __launch_bounds__(NTHR, 2)
k_all(const float* __restrict__ x1, const float* __restrict__ x2,
      const float* __restrict__ ef1, const float* __restrict__ ef2,
      const float* __restrict__ gw,
      const float* __restrict__ Wn, const float* __restrict__ bn,
      const float* __restrict__ We, const float* __restrict__ be,
      const int* __restrict__ ei1, const int* __restrict__ ei2,
      float* __restrict__ M) {
    __shared__ float4 As[16][17];
    __shared__ float4 Bs[16][17];
    float* sred = (float*)Bs;        // phase-A scratch (re-used by GEMM later)

    int t = threadIdx.x;
    int b = blockIdx.x;
    int lane = t & 31, warp = t >> 5;

    // ================= Phase A: coeff rows + zero-fill =====================
    // Block b handles rows {b, b+240, ...}: 9 rows for b<128, else 8.
    // Each thread loads one float4 per row (256 float4 = 1024 floats/row).
    {
        float4 g4 = ((const float4*)gw)[t];
        int nr = (b < 128) ? 9 : 8;
        float4 wv[9];
#pragma unroll
        for (int i = 0; i < 9; i++) {
            if (i < nr) {
                int r = b + NBLK * i;
                const float* W = (r < DIM) ? Wn : We;
                int rr = (r < DIM) ? r : r - DIM;
                wv[i] = ((const float4*)(W + rr * DIM))[t];
            }
        }
        // zero-fill output; stores overlap the in-flight weight loads
        {
            float4 z = make_float4(0.f, 0.f, 0.f, 0.f);
            float4* out4 = (float4*)M;
            for (int i = b * NTHR + t; i < N4; i += NBLK * NTHR) out4[i] = z;
        }
#pragma unroll
        for (int i = 0; i < 9; i++) {
            if (i < nr) {
                float4 a = wv[i];
                float acc = a.x * g4.x + a.y * g4.y + a.z * g4.z + a.w * g4.w;
#pragma unroll
                for (int o = 16; o; o >>= 1) acc += __shfl_xor_sync(0xffffffffu, acc, o);
                if (lane == 0) sred[i * 8 + warp] = acc;
            }
        }
        __syncthreads();
        if (t < nr) {
            float s = 0.f;
#pragma unroll
            for (int j = 0; j < 8; j++) s += sred[t * 8 + j];
            int r = b + NBLK * t;
            if (r < DIM) g_cn[r]       = tanhf(s + bn[r]);
            else         g_ce[r - DIM] = tanhf(s + be[r - DIM]);
        }
    }

    grid_barrier(&g_bar1);

    // ================= Phase B: Me split-K GEMM / Mp =======================
    if (b < GEMM_BLOCKS) {
        // C[m,n] = sum_k ef1[m,k]*ce[k]*ef2[n,k]; 64x64 tile, k-major smem,
        // contiguous 4x4 C tile per thread (2x LDS.128 + 16 FFMA per kk).
        float* Asf = (float*)As;        // row stride 68 floats
        float* Bsf = (float*)Bs;

        int tx = t & 15, ty = t >> 4;
        int bx = b % 3;
        int by = (b / 3) % 3;
        int kz = b / 9;                 // 0..15
        int lr = t >> 2;                // 0..63 (tile row this thread loads)
        int lc = (t & 3) * 4;           // 0,4,8,12 (k-chunk base)
        float acc[4][4] = {};
        int k0 = kz * KC;
        const float* Arow = ef1 + (by * 64 + lr) * DIM;
        const float* Brow = ef2 + (bx * 64 + lr) * DIM;

        for (int kb = k0; kb < k0 + KC; kb += 16) {
            float4 c4 = *(const float4*)(g_ce + kb + lc);
            float4 a4 = *(const float4*)(Arow + kb + lc);
            float4 b4 = *(const float4*)(Brow + kb + lc);
            a4.x *= c4.x; a4.y *= c4.y; a4.z *= c4.z; a4.w *= c4.w;
            Asf[(lc + 0) * 68 + lr] = a4.x;
            Asf[(lc + 1) * 68 + lr] = a4.y;
            Asf[(lc + 2) * 68 + lr] = a4.z;
            Asf[(lc + 3) * 68 + lr] = a4.w;
            Bsf[(lc + 0) * 68 + lr] = b4.x;
            Bsf[(lc + 1) * 68 + lr] = b4.y;
            Bsf[(lc + 2) * 68 + lr] = b4.z;
            Bsf[(lc + 3) * 68 + lr] = b4.w;
            __syncthreads();
#pragma unroll
            for (int kk = 0; kk < 16; kk++) {
                float4 av = As[kk][ty];
                float4 bv = Bs[kk][tx];
                float a[4] = {av.x, av.y, av.z, av.w};
                float bb[4] = {bv.x, bv.y, bv.z, bv.w};
#pragma unroll
                for (int j = 0; j < 4; j++)
#pragma unroll
                    for (int i = 0; i < 4; i++)
                        acc[j][i] += a[j] * bb[i];
            }
            __syncthreads();
        }

        float* outp = g_MePart[kz];
#pragma unroll
        for (int j = 0; j < 4; j++) {
            int m = by * 64 + 4 * ty + j;
            int n = bx * 64 + 4 * tx;
            *(float4*)(outp + m * N_EDGES + n) =
                make_float4(acc[j][0], acc[j][1], acc[j][2], acc[j][3]);
        }
    } else {
        // Mp: 768 warps, 3 outputs per warp (same m, A row reused)
        int w = (b - GEMM_BLOCKS) * 8 + warp;   // 0..767
        int idx0 = w * 3;
        int m = idx0 / N_NODES, n0 = idx0 % N_NODES;  // 48 % 3 == 0 -> same m
        const float4* A  = (const float4*)(x1 + m * DIM);
        const float4* B0 = (const float4*)(x2 + n0 * DIM);
        const float4* C  = (const float4*)g_cn;
        float s0 = 0.f, s1 = 0.f, s2 = 0.f;
#pragma unroll
        for (int i = 0; i < 8; i++) {
            int k = i * 32 + lane;
            float4 a = A[k], c = C[k];
            a.x *= c.x; a.y *= c.y; a.z *= c.z; a.w *= c.w;
            float4 b0 = B0[k], b1 = B0[256 + k], b2 = B0[512 + k];
            s0 += a.x * b0.x + a.y * b0.y + a.z * b0.z + a.w * b0.w;
            s1 += a.x * b1.x + a.y * b1.y + a.z * b1.z + a.w * b1.w;
            s2 += a.x * b2.x + a.y * b2.y + a.z * b2.z + a.w * b2.w;
        }
#pragma unroll
        for (int o = 16; o; o >>= 1) {
            s0 += __shfl_xor_sync(0xffffffffu, s0, o);
            s1 += __shfl_xor_sync(0xffffffffu, s1, o);
            s2 += __shfl_xor_sync(0xffffffffu, s2, o);
        }
        if (lane == 0) {
            g_Mp[idx0 + 0] = softplus_act(s0);
            g_Mp[idx0 + 1] = softplus_act(s1);
            g_Mp[idx0 + 2] = softplus_act(s2);
        }
    }

    grid_barrier(&g_bar2);

    // ================= Phase C: scatter ====================================
    // value for pair (j1,j2) is Me.flat[j2*192+j1]:
    //   M[head2[j2]*48+head1[j1], tail2[j2]*48+tail1[j1]] += act(.)
    for (int idx = b * NTHR + t; idx < EE + NN; idx += NBLK * NTHR) {
        if (idx < EE) {
            float s = 0.f;
#pragma unroll
            for (int z = 0; z < SPLITK; z++) s += g_MePart[z][idx];
            float v = softplus_act(s);
            if (v > 0.f) {
                int j2 = idx / N_EDGES;   // row of Me flat view
                int j1 = idx % N_EDGES;   // col of Me flat view
                int r = ei2[j2] * N_NODES + ei1[j1];                      // heads
                int c = ei2[N_EDGES + j2] * N_NODES + ei1[N_EDGES + j1];  // tails
                atomicAdd(M + r * OUT_DIM + c, v);
            }
        } else {
            int a = idx - EE;
            atomicAdd(M + a * (OUT_DIM + 1), g_Mp[a]);
        }
    }
}

extern "C" void kernel_launch(void* const* d_in, const int* in_sizes, int n_in,
                              void* d_out, int out_size) {
    const float* x1  = (const float*)d_in[0];
    const float* x2  = (const float*)d_in[1];
    const float* ef1 = (const float*)d_in[2];
    const float* ef2 = (const float*)d_in[3];
    const float* gw  = (const float*)d_in[4];
    const float* Wn  = (const float*)d_in[5];
    const float* bn  = (const float*)d_in[6];
    const float* We  = (const float*)d_in[7];
    const float* be  = (const float*)d_in[8];
    const int*   ei1 = (const int*)d_in[9];
    const int*   ei2 = (const int*)d_in[10];
    float* M = (float*)d_out;

    k_all<<<NBLK, NTHR>>>(x1, x2, ef1, ef2, gw, Wn, bn, We, be, ei1, ei2, M);
}